// round 7
// baseline (speedup 1.0000x reference)
#include <cuda_runtime.h>
#include <cuda_fp16.h>
#include <cuda_bf16.h>

#define NSTEP 730
#define NG    2000
#define MU    16
#define NOUT  500
#define PRECS 1e-5f

#define SPf 96000   // params stride per t, in floats (NG*3*MU)
#define SXf 6000    // x stride per t, in floats (NG*3)
#define NLANE 32000 // NG*MU

// Per-lane q (scaled by Ai/16), fp16: [t][g*16+m]  (46.7 MB scratch)
__device__ __half g_qh[NSTEP * NLANE];
// Reduced: qA[t][g]
__device__ float g_qA[NSTEP * NG];

// ---------------------------------------------------------------------------
// Kernel 1: HBV scan. 125 blocks x 256 threads = 32,000 exactly.
// x staged via double-buffered smem (192 coalesced floats / 4-step batch);
// params prefetched into registers; q stored per-lane as fp16.
// ---------------------------------------------------------------------------
__global__ __launch_bounds__(256)
void hbv_scan_kernel(const float* __restrict__ x,          // (730, 2000, 3)
                     const float* __restrict__ params,     // (730, 2000, 3, 16)
                     const float* __restrict__ wl,         // (2000, 13, 16)
                     const float* __restrict__ Ai,         // (2000,)
                     const float* __restrict__ Acb)        // (2000,)
{
    __shared__ float sx[2][192];   // [buf][u*48 + g_local*3 + c]

    int tid = blockIdx.x * 256 + threadIdx.x;   // in [0, 32000)
    int g = tid >> 4;
    int m = tid & 15;
    int g0 = blockIdx.x * 16;                   // block's first grid cell
    int gl3 = (threadIdx.x >> 4) * 3;           // g_local * 3

    int si = threadIdx.x;                       // stage index
    int su = si / 48;                           // 0..3 (valid si<192)
    int sj = si % 48;
    bool stager = si < 192;

    // ---- per-(g,m) waterloss parameters, scaled by SCA2 ----
    const float* w = wl + (size_t)g * 13 * MU + m;
    float parFC    = 50.0f   + w[0  * MU] * (1000.0f - 50.0f);
    float parK1    = 0.01f   + w[1  * MU] * (0.5f   - 0.01f);
    float parK2    = 0.001f  + w[2  * MU] * (0.2f   - 0.001f);
    float parLP    = 0.2f    + w[3  * MU] * (1.0f   - 0.2f);
    float parPERC  =           w[4  * MU] * 10.0f;
    float parUZL   =           w[5  * MU] * 100.0f;
    float parTT    = -2.5f   + w[6  * MU] * 5.0f;
    float parCFMAX = 0.5f    + w[7  * MU] * (10.0f  - 0.5f);
    float parCFR   =           w[8  * MU] * 0.1f;
    float parCWH   =           w[9  * MU] * 0.2f;
    float parC     =           w[10 * MU] * 1.0f;
    float parTR    =           w[11 * MU] * 20.0f;
    float parAc    =           w[12 * MU] * 2500.0f;

    float Ac  = Acb[g];
    float Aig = Ai[g] * 0.0625f;

    float rf;
    {
        float c1 = fminf(fmaxf((Ac - parAc) * (1.0f / 1000.0f), -1.0f), 1.0f);
        float ea = fminf(fmaxf(-(Ac - 2500.0f) * (1.0f / 50.0f), -10.0f), 0.0f);
        float e  = expf(ea);
        rf = (Ac < 2500.0f) ? (c1 * parTR) : (e * parTR);
    }

    float invFC   = 1.0f / parFC;
    float invLPFC = 1.0f / (parLP * parFC);
    float CFRCF   = parCFR * parCFMAX;

    float SNOWPACK = 0.001f, MELTWATER = 0.001f, SM = 0.001f, SUZ = 0.001f, SLZ = 0.001f;

    const float* pp = params + g * 48 + m;

    // initial x stage: t = 0..3 into buffer 0
    if (stager) sx[0][si] = x[(size_t)su * SXf + g0 * 3 + sj];

    // initial params: t = 0..3
    float cB[4], cK[4], cBE[4];
    #pragma unroll
    for (int u = 0; u < 4; u++) {
        cB[u]  = __ldcs(pp + u * SPf);
        cK[u]  = __ldcs(pp + u * SPf + 16);
        cBE[u] = __ldcs(pp + u * SPf + 32);
    }
    __syncthreads();

    const float* pf = pp + 4 * SPf;   // param prefetch base (row tb+4)
    __half* qs = g_qh + tid;          // per-lane output column
    int cb = 0;

#define HBV_STEP(rbv, rkv, rbev, Ptv, Ttv, Etv, QDST) do {                     \
    float parBETA   = fmaf((rbv),  5.0f,  1.0f);                               \
    float parK0     = fmaf((rkv),  0.85f, 0.05f);                              \
    float parBETAET = fmaf((rbev), 4.7f,  0.3f);                               \
    float RAIN = ((Ttv) >= parTT) ? (Ptv) : 0.0f;                              \
    SNOWPACK += (Ptv) - RAIN;                                                  \
    float melt = fminf(fmaxf(parCFMAX * ((Ttv) - parTT), 0.0f), SNOWPACK);     \
    MELTWATER += melt;  SNOWPACK -= melt;                                      \
    float refr = fminf(fmaxf(CFRCF * (parTT - (Ttv)), 0.0f), MELTWATER);       \
    SNOWPACK += refr;   MELTWATER -= refr;                                     \
    float tosoil = fmaxf(MELTWATER - parCWH * SNOWPACK, 0.0f);                 \
    MELTWATER -= tosoil;                                                       \
    float sw = __saturatef(__powf(SM * invFC, parBETA));                       \
    float rt_ = RAIN + tosoil;                                                 \
    float recharge = rt_ * sw;                                                 \
    SM += rt_ - recharge;                                                      \
    float excess = fmaxf(SM - parFC, 0.0f);                                    \
    SM -= excess;                                                              \
    float ef = __saturatef(__powf(SM * invLPFC, parBETAET));                   \
    float ETact = fminf(SM, (Etv) * ef);                                       \
    SM = fmaxf(SM - ETact, PRECS);                                             \
    float cap = fminf(SLZ, parC * SLZ * (1.0f - fminf(SM * invFC, 1.0f)));     \
    SM  = fmaxf(SM + cap, PRECS);                                              \
    SLZ = fmaxf(SLZ - cap, PRECS);                                             \
    SUZ += recharge + excess;                                                  \
    float PERC = fminf(SUZ, parPERC);                                          \
    SUZ -= PERC;                                                               \
    float Q0 = parK0 * fmaxf(SUZ - parUZL, 0.0f);                              \
    SUZ -= Q0;                                                                 \
    float Q1 = parK1 * SUZ;                                                    \
    SUZ -= Q1;                                                                 \
    SLZ = fmaxf(SLZ + PERC + rf, 0.0f);                                        \
    float Q2 = parK2 * SLZ;                                                    \
    SLZ -= Q2;                                                                 \
    (QDST) = __float2half_rn((Q0 + Q1 + Q2) * Aig);                            \
} while (0)

    // Main loop: tb = 0..720 (steps t=0..723); prefetch t=tb+4..tb+7 (<=727).
    for (int tb = 0; tb <= 720; tb += 4) {
        // param prefetch (registers)
        float nB[4], nK[4], nBE[4];
        #pragma unroll
        for (int u = 0; u < 4; u++) {
            nB[u]  = __ldcs(pf + u * SPf);
            nK[u]  = __ldcs(pf + u * SPf + 16);
            nBE[u] = __ldcs(pf + u * SPf + 32);
        }
        pf += 4 * SPf;

        // x prefetch (to register, stored to smem after compute)
        float xv = 0.0f;
        if (stager) xv = x[(size_t)(tb + 4 + su) * SXf + g0 * 3 + sj];

        // compute 4 steps from current smem buffer + register params
        #pragma unroll
        for (int u = 0; u < 4; u++) {
            float Pt = sx[cb][u * 48 + gl3 + 0];
            float Tt = sx[cb][u * 48 + gl3 + 1];
            float Et = sx[cb][u * 48 + gl3 + 2];
            HBV_STEP(cB[u], cK[u], cBE[u], Pt, Tt, Et, qs[u * NLANE]);
        }
        qs += 4 * NLANE;

        // commit x prefetch to the other buffer, then sync
        if (stager) sx[cb ^ 1][si] = xv;
        __syncthreads();
        cb ^= 1;

        #pragma unroll
        for (int u = 0; u < 4; u++) { cB[u] = nB[u]; cK[u] = nK[u]; cBE[u] = nBE[u]; }
    }

    // Tail: cB/cK/cBE and sx[cb] hold t = 724..727; pf -> row 728.
    float tB0 = __ldcs(pf + 0),   tK0 = __ldcs(pf + 16),        tBE0 = __ldcs(pf + 32);
    float tB1 = __ldcs(pf + SPf), tK1 = __ldcs(pf + SPf + 16),  tBE1 = __ldcs(pf + SPf + 32);
    const float* xg = x + (size_t)728 * SXf + g * 3;
    float tP0 = xg[0],   tT0 = xg[1],       tE0 = xg[2];
    float tP1 = xg[SXf], tT1 = xg[SXf + 1], tE1 = xg[SXf + 2];

    #pragma unroll
    for (int u = 0; u < 4; u++) {
        float Pt = sx[cb][u * 48 + gl3 + 0];
        float Tt = sx[cb][u * 48 + gl3 + 1];
        float Et = sx[cb][u * 48 + gl3 + 2];
        HBV_STEP(cB[u], cK[u], cBE[u], Pt, Tt, Et, qs[u * NLANE]);
    }
    HBV_STEP(tB0, tK0, tBE0, tP0, tT0, tE0, qs[4 * NLANE]);
    HBV_STEP(tB1, tK1, tBE1, tP1, tT1, tE1, qs[5 * NLANE]);

#undef HBV_STEP
}

// ---------------------------------------------------------------------------
// Kernel 1b: mu-mean. One thread per (t, g): sum 16 consecutive fp16 lanes.
// ---------------------------------------------------------------------------
__device__ __forceinline__ float sum_h2(unsigned u) {
    __half2 h = *reinterpret_cast<__half2*>(&u);
    float2 f = __half22float2(h);
    return f.x + f.y;
}

__global__ __launch_bounds__(256)
void mu_reduce_kernel() {
    int o = blockIdx.x * 256 + threadIdx.x;     // o = t*NG + g
    if (o >= NSTEP * NG) return;
    const uint4* p = reinterpret_cast<const uint4*>(g_qh + (size_t)o * 16);
    uint4 a = __ldcs(p);
    uint4 b = __ldcs(p + 1);
    float s = (sum_h2(a.x) + sum_h2(a.y)) + (sum_h2(a.z) + sum_h2(a.w))
            + (sum_h2(b.x) + sum_h2(b.y)) + (sum_h2(b.z) + sum_h2(b.w));
    g_qA[o] = s;
}

// ---------------------------------------------------------------------------
// Kernel 2b: zero output (poisoned to 0xAA; GEMM accumulates with atomics)
// ---------------------------------------------------------------------------
__global__ void zero_out_kernel(float* __restrict__ out, int n) {
    int i = blockIdx.x * blockDim.x + threadIdx.x;
    if (i < n) out[i] = 0.0f;
}

// ---------------------------------------------------------------------------
// Kernel 2: out[t][o] += sum_{g in chunk} qA[t][g] * idx[g][o]
// SGEMM M=730, N=500, K=2000. BM=64, BN=64, BK=32, 256 threads, 4x4/thread,
// split-K=6 (576 blocks), double-buffered smem: loads overlap FFMA.
// ---------------------------------------------------------------------------
#define BM 64
#define BN 64
#define BK 32
#define SPLITK 6
#define KCHUNK 336   // 336*6 = 2016 >= 2000

__global__ __launch_bounds__(256)
void agg_gemm_kernel(const float* __restrict__ idxm,  // (2000, 500)
                     float* __restrict__ out)         // (730, 500)
{
    __shared__ float sA[2][BM][BK + 1];   // m-major, padded
    __shared__ float sB[2][BK][BN];       // k-major

    int bm = blockIdx.y * BM;
    int bn = blockIdx.x * BN;
    int kstart = blockIdx.z * KCHUNK;
    int kend   = min(kstart + KCHUNK, NG);

    int tid = threadIdx.x;
    int tx = tid & 15;   // n groups of 4
    int ty = tid >> 4;   // m groups of 4

    float acc[4][4] = {};

    // initial tile load (buffer 0)
    #pragma unroll
    for (int r = 0; r < 8; r++) {
        int i = tid + 256 * r;
        int mm = i >> 5, kk = i & 31;
        int t = bm + mm, k = kstart + kk;
        sA[0][mm][kk] = (t < NSTEP && k < kend) ? g_qA[(size_t)t * NG + k] : 0.0f;
    }
    #pragma unroll
    for (int r = 0; r < 8; r++) {
        int i = tid + 256 * r;
        int kk = i >> 6, nn = i & 63;
        int k = kstart + kk, o = bn + nn;
        sB[0][kk][nn] = (k < kend && o < NOUT) ? idxm[(size_t)k * NOUT + o] : 0.0f;
    }
    __syncthreads();

    int buf = 0;
    for (int k0 = kstart; k0 < kend; k0 += BK) {
        int k1 = k0 + BK;
        bool more = k1 < kend;

        // stage next tile into registers (LDGs issue here, overlap compute)
        float ra[8], rb[8];
        if (more) {
            #pragma unroll
            for (int r = 0; r < 8; r++) {
                int i = tid + 256 * r;
                int mm = i >> 5, kk = i & 31;
                int t = bm + mm, k = k1 + kk;
                ra[r] = (t < NSTEP && k < kend) ? g_qA[(size_t)t * NG + k] : 0.0f;
            }
            #pragma unroll
            for (int r = 0; r < 8; r++) {
                int i = tid + 256 * r;
                int kk = i >> 6, nn = i & 63;
                int k = k1 + kk, o = bn + nn;
                rb[r] = (k < kend && o < NOUT) ? idxm[(size_t)k * NOUT + o] : 0.0f;
            }
        }

        // compute on current buffer
        #pragma unroll 8
        for (int k = 0; k < BK; k++) {
            float aa[4];
            #pragma unroll
            for (int i = 0; i < 4; i++) aa[i] = sA[buf][ty * 4 + i][k];
            float4 b4 = *reinterpret_cast<const float4*>(&sB[buf][k][tx * 4]);
            float bb[4] = {b4.x, b4.y, b4.z, b4.w};
            #pragma unroll
            for (int i = 0; i < 4; i++)
                #pragma unroll
                for (int j = 0; j < 4; j++)
                    acc[i][j] = fmaf(aa[i], bb[j], acc[i][j]);
        }

        // commit staged tile to the other buffer
        if (more) {
            #pragma unroll
            for (int r = 0; r < 8; r++) {
                int i = tid + 256 * r;
                int mm = i >> 5, kk = i & 31;
                sA[buf ^ 1][mm][kk] = ra[r];
            }
            #pragma unroll
            for (int r = 0; r < 8; r++) {
                int i = tid + 256 * r;
                int kk = i >> 6, nn = i & 63;
                sB[buf ^ 1][kk][nn] = rb[r];
            }
        }
        __syncthreads();
        buf ^= 1;
    }

    #pragma unroll
    for (int i = 0; i < 4; i++) {
        int t = bm + ty * 4 + i;
        if (t >= NSTEP) continue;
        #pragma unroll
        for (int j = 0; j < 4; j++) {
            int o = bn + tx * 4 + j;
            if (o < NOUT) atomicAdd(&out[(size_t)t * NOUT + o], acc[i][j]);
        }
    }
}

// ---------------------------------------------------------------------------
extern "C" void kernel_launch(void* const* d_in, const int* in_sizes, int n_in,
                              void* d_out, int out_size) {
    const float* x      = (const float*)d_in[0];  // (730,2000,3)
    const float* params = (const float*)d_in[1];  // (730,2000,3,16)
    const float* wl     = (const float*)d_in[2];  // (2000,13,16)
    const float* Ai     = (const float*)d_in[3];  // (2000,)
    const float* Acb    = (const float*)d_in[4];  // (2000,)
    const float* idxm   = (const float*)d_in[5];  // (2000,500)
    float* out = (float*)d_out;                   // (730,500,1)

    hbv_scan_kernel<<<125, 256>>>(x, params, wl, Ai, Acb);

    int nr = NSTEP * NG;
    mu_reduce_kernel<<<(nr + 255) / 256, 256>>>();

    int n = NSTEP * NOUT;
    zero_out_kernel<<<(n + 511) / 512, 512>>>(out, n);

    dim3 grid((NOUT + BN - 1) / BN, (NSTEP + BM - 1) / BM, SPLITK);
    agg_gemm_kernel<<<grid, 256>>>(idxm, out);
}

// round 8
// speedup vs baseline: 1.0608x; 1.0608x over previous
#include <cuda_runtime.h>
#include <cuda_bf16.h>

#define NSTEP 730
#define NG    2000
#define MU    16
#define NOUT  500
#define PRECS 1e-5f

#define SPf 96000   // params stride per t, in floats (NG*3*MU)
#define SXf 6000    // x stride per t, in floats (NG*3)
#define NLANE 32000 // NG*MU

// Per-lane q (scaled by Ai/16): [t][g*16+m]
__device__ float g_q[NSTEP * NLANE];
// Reduced: qA[t][g]
__device__ float g_qA[NSTEP * NG];

// ---------------------------------------------------------------------------
// One HBV step for one lane. Returns q. Fully inlined; two calls per thread
// interleave as ILP.
// ---------------------------------------------------------------------------
__device__ __forceinline__ float hbv_step(
    float rb, float rk, float rbe, float Pt, float Tt, float Et,
    float parTT, float parCFMAX, float CFRCF, float parCWH,
    float invFC, float parFC, float invLPFC, float parC,
    float parPERC, float parUZL, float parK1, float parK2, float rf,
    float& SNOWPACK, float& MELTWATER, float& SM, float& SUZ, float& SLZ)
{
    float parBETA   = fmaf(rb,  5.0f,  1.0f);
    float parK0     = fmaf(rk,  0.85f, 0.05f);
    float parBETAET = fmaf(rbe, 4.7f,  0.3f);

    float RAIN = (Tt >= parTT) ? Pt : 0.0f;
    SNOWPACK += Pt - RAIN;
    float melt = fminf(fmaxf(parCFMAX * (Tt - parTT), 0.0f), SNOWPACK);
    MELTWATER += melt;  SNOWPACK -= melt;
    float refr = fminf(fmaxf(CFRCF * (parTT - Tt), 0.0f), MELTWATER);
    SNOWPACK += refr;   MELTWATER -= refr;
    float tosoil = fmaxf(MELTWATER - parCWH * SNOWPACK, 0.0f);
    MELTWATER -= tosoil;

    float sw = __saturatef(__powf(SM * invFC, parBETA));
    float rt_ = RAIN + tosoil;
    float recharge = rt_ * sw;
    SM += rt_ - recharge;
    float excess = fmaxf(SM - parFC, 0.0f);
    SM -= excess;

    float ef = __saturatef(__powf(SM * invLPFC, parBETAET));
    float ETact = fminf(SM, Et * ef);
    SM = fmaxf(SM - ETact, PRECS);

    float cap = fminf(SLZ, parC * SLZ * (1.0f - fminf(SM * invFC, 1.0f)));
    SM  = fmaxf(SM + cap, PRECS);
    SLZ = fmaxf(SLZ - cap, PRECS);

    SUZ += recharge + excess;
    float PERC = fminf(SUZ, parPERC);
    SUZ -= PERC;
    float Q0 = parK0 * fmaxf(SUZ - parUZL, 0.0f);
    SUZ -= Q0;
    float Q1 = parK1 * SUZ;
    SUZ -= Q1;
    SLZ = fmaxf(SLZ + PERC + rf, 0.0f);
    float Q2 = parK2 * SLZ;
    SLZ -= Q2;
    return Q0 + Q1 + Q2;
}

// ---------------------------------------------------------------------------
// Kernel 1: HBV scan. 16,000 threads (125 x 128); each thread owns TWO
// adjacent mu-lanes (m = 2j, 2j+1) -> float2 param loads, shared x loads,
// 2 independent chains of ILP per thread. Depth-4 register pipeline.
// ---------------------------------------------------------------------------
__global__ __launch_bounds__(128)
void hbv_scan_kernel(const float* __restrict__ x,          // (730, 2000, 3)
                     const float* __restrict__ params,     // (730, 2000, 3, 16)
                     const float* __restrict__ wl,         // (2000, 13, 16)
                     const float* __restrict__ Ai,         // (2000,)
                     const float* __restrict__ Acb)        // (2000,)
{
    int tid = blockIdx.x * 128 + threadIdx.x;   // [0, 16000)
    int g = tid >> 3;
    int j = tid & 7;                            // lanes m = 2j, 2j+1

    // ---- waterloss parameters (float2 = both lanes), scaled by SCA2 ----
    const float* w = wl + (size_t)g * 208 + 2 * j;   // 13*16 = 208
#define LD2(P) (*reinterpret_cast<const float2*>(P))
    float2 r;
    r = LD2(w + 0*16);  float2 parFC    = {fmaf(r.x, 950.0f, 50.0f),  fmaf(r.y, 950.0f, 50.0f)};
    r = LD2(w + 1*16);  float2 parK1    = {fmaf(r.x, 0.49f, 0.01f),   fmaf(r.y, 0.49f, 0.01f)};
    r = LD2(w + 2*16);  float2 parK2    = {fmaf(r.x, 0.199f, 0.001f), fmaf(r.y, 0.199f, 0.001f)};
    r = LD2(w + 3*16);  float2 parLP    = {fmaf(r.x, 0.8f, 0.2f),     fmaf(r.y, 0.8f, 0.2f)};
    r = LD2(w + 4*16);  float2 parPERC  = {r.x * 10.0f,               r.y * 10.0f};
    r = LD2(w + 5*16);  float2 parUZL   = {r.x * 100.0f,              r.y * 100.0f};
    r = LD2(w + 6*16);  float2 parTT    = {fmaf(r.x, 5.0f, -2.5f),    fmaf(r.y, 5.0f, -2.5f)};
    r = LD2(w + 7*16);  float2 parCFMAX = {fmaf(r.x, 9.5f, 0.5f),     fmaf(r.y, 9.5f, 0.5f)};
    r = LD2(w + 8*16);  float2 parCFR   = {r.x * 0.1f,                r.y * 0.1f};
    r = LD2(w + 9*16);  float2 parCWH   = {r.x * 0.2f,                r.y * 0.2f};
    r = LD2(w + 10*16); float2 parC     = {r.x,                       r.y};
    r = LD2(w + 11*16); float2 parTR    = {r.x * 20.0f,               r.y * 20.0f};
    r = LD2(w + 12*16); float2 parAc    = {r.x * 2500.0f,             r.y * 2500.0f};

    float Ac  = Acb[g];
    float Aig = Ai[g] * 0.0625f;

    float2 rf;
    {
        float ea = expf(fminf(fmaxf(-(Ac - 2500.0f) * (1.0f / 50.0f), -10.0f), 0.0f));
        float c1x = fminf(fmaxf((Ac - parAc.x) * (1.0f / 1000.0f), -1.0f), 1.0f);
        float c1y = fminf(fmaxf((Ac - parAc.y) * (1.0f / 1000.0f), -1.0f), 1.0f);
        rf.x = (Ac < 2500.0f) ? (c1x * parTR.x) : (ea * parTR.x);
        rf.y = (Ac < 2500.0f) ? (c1y * parTR.y) : (ea * parTR.y);
    }

    float2 invFC   = {1.0f / parFC.x, 1.0f / parFC.y};
    float2 invLPFC = {1.0f / (parLP.x * parFC.x), 1.0f / (parLP.y * parFC.y)};
    float2 CFRCF   = {parCFR.x * parCFMAX.x, parCFR.y * parCFMAX.y};

    // state (2 lanes)
    float SPx = 0.001f, MWx = 0.001f, SMx = 0.001f, SUx = 0.001f, SLx = 0.001f;
    float SPy = 0.001f, MWy = 0.001f, SMy = 0.001f, SUy = 0.001f, SLy = 0.001f;

    const float* pp = params + g * 48 + 2 * j;   // float2 loads; stride SPf per t
    const float* xp = x + g * 3;

    float2 cB[4], cK[4], cBE[4];
    float  cP[4], cT[4], cE[4];

    #pragma unroll
    for (int u = 0; u < 4; u++) {
        cB[u]  = LD2(pp + u * SPf);
        cK[u]  = LD2(pp + u * SPf + 16);
        cBE[u] = LD2(pp + u * SPf + 32);
        cP[u]  = xp[u * SXf + 0];
        cT[u]  = xp[u * SXf + 1];
        cE[u]  = xp[u * SXf + 2];
    }

    const float* pf = pp + 4 * SPf;
    const float* xf = xp + 4 * SXf;
    float* qs = g_q + 2 * tid;     // float2 store target, stride NLANE per t

#define DO_STEP(u, DST) do {                                                   \
    float qx = hbv_step(cB[u].x, cK[u].x, cBE[u].x, cP[u], cT[u], cE[u],       \
        parTT.x, parCFMAX.x, CFRCF.x, parCWH.x, invFC.x, parFC.x, invLPFC.x,   \
        parC.x, parPERC.x, parUZL.x, parK1.x, parK2.x, rf.x,                   \
        SPx, MWx, SMx, SUx, SLx);                                              \
    float qy = hbv_step(cB[u].y, cK[u].y, cBE[u].y, cP[u], cT[u], cE[u],       \
        parTT.y, parCFMAX.y, CFRCF.y, parCWH.y, invFC.y, parFC.y, invLPFC.y,   \
        parC.y, parPERC.y, parUZL.y, parK1.y, parK2.y, rf.y,                   \
        SPy, MWy, SMy, SUy, SLy);                                              \
    float2 qv = {qx * Aig, qy * Aig};                                          \
    *reinterpret_cast<float2*>(DST) = qv;                                      \
} while (0)

    // Main loop: tb = 0..720 (steps t=0..723); prefetch rows tb+4..tb+7 (<=727).
    for (int tb = 0; tb <= 720; tb += 4) {
        float2 nB[4], nK[4], nBE[4];
        float  nP[4], nT[4], nE[4];
        #pragma unroll
        for (int u = 0; u < 4; u++) {
            nB[u]  = LD2(pf + u * SPf);
            nK[u]  = LD2(pf + u * SPf + 16);
            nBE[u] = LD2(pf + u * SPf + 32);
            nP[u]  = xf[u * SXf + 0];
            nT[u]  = xf[u * SXf + 1];
            nE[u]  = xf[u * SXf + 2];
        }
        pf += 4 * SPf;
        xf += 4 * SXf;

        #pragma unroll
        for (int u = 0; u < 4; u++)
            DO_STEP(u, qs + u * NLANE);
        qs += 4 * NLANE;

        #pragma unroll
        for (int u = 0; u < 4; u++) {
            cB[u] = nB[u]; cK[u] = nK[u]; cBE[u] = nBE[u];
            cP[u] = nP[u]; cT[u] = nT[u]; cE[u]  = nE[u];
        }
    }

    // Tail: c holds t=724..727; pf/xf -> row 728. Steps 728, 729 loaded fresh.
    float2 tB[2], tK[2], tBE[2];
    float  tP[2], tT[2], tE[2];
    #pragma unroll
    for (int u = 0; u < 2; u++) {
        tB[u]  = LD2(pf + u * SPf);
        tK[u]  = LD2(pf + u * SPf + 16);
        tBE[u] = LD2(pf + u * SPf + 32);
        tP[u]  = xf[u * SXf + 0];
        tT[u]  = xf[u * SXf + 1];
        tE[u]  = xf[u * SXf + 2];
    }

    #pragma unroll
    for (int u = 0; u < 4; u++)
        DO_STEP(u, qs + u * NLANE);
    qs += 4 * NLANE;

    #pragma unroll
    for (int u = 0; u < 2; u++) {
        cB[u] = tB[u]; cK[u] = tK[u]; cBE[u] = tBE[u];
        cP[u] = tP[u]; cT[u] = tT[u]; cE[u]  = tE[u];
    }
    #pragma unroll
    for (int u = 0; u < 2; u++)
        DO_STEP(u, qs + u * NLANE);

#undef DO_STEP
#undef LD2
}

// ---------------------------------------------------------------------------
// Kernel 1b: mu-mean + output zeroing (fused). One thread per (t, g).
// ---------------------------------------------------------------------------
__global__ __launch_bounds__(256)
void mu_reduce_kernel(float* __restrict__ out) {
    int o = blockIdx.x * 256 + threadIdx.x;     // o = t*NG + g
    if (o < NSTEP * NOUT) out[o] = 0.0f;        // zero output (poisoned 0xAA)
    if (o >= NSTEP * NG) return;
    const float4* p = reinterpret_cast<const float4*>(g_q + (size_t)o * 16);
    float4 a = __ldcs(p + 0);
    float4 b = __ldcs(p + 1);
    float4 c = __ldcs(p + 2);
    float4 d = __ldcs(p + 3);
    float s = ((a.x + a.y) + (a.z + a.w)) + ((b.x + b.y) + (b.z + b.w))
            + ((c.x + c.y) + (c.z + c.w)) + ((d.x + d.y) + (d.z + d.w));
    g_qA[o] = s;
}

// ---------------------------------------------------------------------------
// Kernel 2: out[t][o] += sum_{g in chunk} qA[t][g] * idx[g][o]
// SGEMM M=730, N=500, K=2000. BM=64, BN=64, BK=32, 256 threads, 4x4/thread,
// plain FFMA, split-K=6 (576 blocks) — round-6 winner, unchanged.
// ---------------------------------------------------------------------------
#define BM 64
#define BN 64
#define BK 32
#define SPLITK 6
#define KCHUNK 336   // 336*6 = 2016 >= 2000

__global__ __launch_bounds__(256)
void agg_gemm_kernel(const float* __restrict__ idxm,  // (2000, 500)
                     float* __restrict__ out)         // (730, 500)
{
    __shared__ float sA[BM][BK + 1];
    __shared__ float sB[BK][BN];

    int bm = blockIdx.y * BM;
    int bn = blockIdx.x * BN;
    int kstart = blockIdx.z * KCHUNK;
    int kend   = min(kstart + KCHUNK, NG);

    int tid = threadIdx.x;
    int tx = tid & 15;
    int ty = tid >> 4;

    float acc[4][4] = {};

    for (int k0 = kstart; k0 < kend; k0 += BK) {
        #pragma unroll
        for (int i = tid; i < BM * BK; i += 256) {
            int mm = i >> 5;
            int kk = i & 31;
            int t = bm + mm;
            int k = k0 + kk;
            sA[mm][kk] = (t < NSTEP && k < kend) ? g_qA[(size_t)t * NG + k] : 0.0f;
        }
        #pragma unroll
        for (int i = tid; i < BK * BN; i += 256) {
            int kk = i >> 6;
            int nn = i & 63;
            int k = k0 + kk;
            int o = bn + nn;
            sB[kk][nn] = (k < kend && o < NOUT) ? idxm[(size_t)k * NOUT + o] : 0.0f;
        }
        __syncthreads();

        #pragma unroll 8
        for (int k = 0; k < BK; k++) {
            float aa[4];
            #pragma unroll
            for (int i = 0; i < 4; i++) aa[i] = sA[ty * 4 + i][k];
            float4 b = *reinterpret_cast<const float4*>(&sB[k][tx * 4]);
            float bb[4] = {b.x, b.y, b.z, b.w};
            #pragma unroll
            for (int i = 0; i < 4; i++)
                #pragma unroll
                for (int j = 0; j < 4; j++)
                    acc[i][j] = fmaf(aa[i], bb[j], acc[i][j]);
        }
        __syncthreads();
    }

    #pragma unroll
    for (int i = 0; i < 4; i++) {
        int t = bm + ty * 4 + i;
        if (t >= NSTEP) continue;
        #pragma unroll
        for (int j = 0; j < 4; j++) {
            int o = bn + tx * 4 + j;
            if (o < NOUT) atomicAdd(&out[(size_t)t * NOUT + o], acc[i][j]);
        }
    }
}

// ---------------------------------------------------------------------------
extern "C" void kernel_launch(void* const* d_in, const int* in_sizes, int n_in,
                              void* d_out, int out_size) {
    const float* x      = (const float*)d_in[0];  // (730,2000,3)
    const float* params = (const float*)d_in[1];  // (730,2000,3,16)
    const float* wl     = (const float*)d_in[2];  // (2000,13,16)
    const float* Ai     = (const float*)d_in[3];  // (2000,)
    const float* Acb    = (const float*)d_in[4];  // (2000,)
    const float* idxm   = (const float*)d_in[5];  // (2000,500)
    float* out = (float*)d_out;                   // (730,500,1)

    hbv_scan_kernel<<<125, 128>>>(x, params, wl, Ai, Acb);

    int nr = NSTEP * NG;
    mu_reduce_kernel<<<(nr + 255) / 256, 256>>>(out);

    dim3 grid((NOUT + BN - 1) / BN, (NSTEP + BM - 1) / BM, SPLITK);
    agg_gemm_kernel<<<grid, 256>>>(idxm, out);
}